// round 3
// baseline (speedup 1.0000x reference)
#include <cuda_runtime.h>
#include <cuda_fp16.h>
#include <stdint.h>

// Problem constants
#define B_ 16384
#define T_ 32
#define I_ 32
#define H_ 256
#define C_ 12

#define MT 128          // batch-tile rows per CTA
#define NTHREADS 512    // 16 warps: 2 (M) x 8 (N)
#define SB 264          // padded smem stride (halfs) for 256-wide rows (conflict-free)
#define SWI 36          // padded stride for w_ih0 (32-wide rows)

// Inter-layer scratch (static device globals; no runtime allocation)
__device__ __align__(16) __half g_h1 [(size_t)B_ * T_ * H_];   // layer0 output, fp16
__device__ __align__(16) __half g_xw1[(size_t)B_ * T_ * H_];   // layer1 input projection, fp16

// ---------------------------------------------------------------------------
// m16n8k16 fp16 mma with fp32 accumulate (Ampere-layout fragments)
// ---------------------------------------------------------------------------
__device__ __forceinline__ void mma16816(float c[4], const uint32_t a[4], const uint32_t b[2]) {
    asm volatile(
        "mma.sync.aligned.m16n8k16.row.col.f32.f16.f16.f32 "
        "{%0,%1,%2,%3}, {%4,%5,%6,%7}, {%8,%9}, {%0,%1,%2,%3};\n"
        : "+f"(c[0]), "+f"(c[1]), "+f"(c[2]), "+f"(c[3])
        : "r"(a[0]), "r"(a[1]), "r"(a[2]), "r"(a[3]), "r"(b[0]), "r"(b[1]));
}

__device__ __forceinline__ uint32_t ldb32(const __half* p) { return *(const uint32_t*)p; }

// acc[mi][ni][4] += A[128 x KTOT] * B^T, where Bs is [256][KTOT] row-major (n,k)
// Warp tile: 64 (M) x 32 (N); fragment addresses computed manually (no ldmatrix).
template<int KTOT, int AST, int BST>
__device__ __forceinline__ void warp_gemm(const __half* __restrict__ As,
                                          const __half* __restrict__ Bs,
                                          float (&acc)[4][4][4],
                                          int wm, int wn, int lane)
{
    const int grp = lane >> 2, tig = lane & 3;
    #pragma unroll
    for (int k0 = 0; k0 < KTOT; k0 += 16) {
        uint32_t a[4][4];
        #pragma unroll
        for (int mi = 0; mi < 4; mi++) {
            const __half* ap = As + (wm * 64 + mi * 16 + grp) * AST + k0 + 2 * tig;
            a[mi][0] = ldb32(ap);
            a[mi][1] = ldb32(ap + 8 * AST);
            a[mi][2] = ldb32(ap + 8);
            a[mi][3] = ldb32(ap + 8 * AST + 8);
        }
        #pragma unroll
        for (int ni = 0; ni < 4; ni++) {
            const __half* bp = Bs + (wn * 32 + ni * 8 + grp) * BST + k0 + 2 * tig;
            uint32_t b[2];
            b[0] = ldb32(bp);
            b[1] = ldb32(bp + 8);
            #pragma unroll
            for (int mi = 0; mi < 4; mi++)
                mma16816(acc[mi][ni], a[mi], b);
        }
    }
}

// ---------------------------------------------------------------------------
// Kernel 1: layer0 fused (input projection + recurrence), h1 -> g_h1 (fp16)
// smem: Whh0 [256][264] fp16, H [128][264] fp16, Wih0 [256][36] fp16,
//       X [128][32] fp16, bias [256] f32   => 230400 B
// ---------------------------------------------------------------------------
__global__ void __launch_bounds__(NTHREADS, 1)
layer0_kernel(const float* __restrict__ x, const float* __restrict__ w_ih,
              const float* __restrict__ w_hh, const float* __restrict__ b_ih,
              const float* __restrict__ b_hh)
{
    extern __shared__ char sm[];
    __half* Whhs = (__half*)sm;               // 256*SB
    __half* Hs   = Whhs + 256 * SB;           // MT*SB
    __half* Wihs = Hs + MT * SB;              // 256*SWI
    __half* Xs   = Wihs + 256 * SWI;          // MT*32
    float*  bs   = (float*)(Xs + MT * 32);    // 256

    const int tid = threadIdx.x;
    const int wid = tid >> 5, lane = tid & 31;
    const int wm = wid >> 3, wn = wid & 7;
    const int grp = lane >> 2, tig = lane & 3;
    const int b0 = blockIdx.x * MT;

    for (int e = tid; e < 256 * 256; e += NTHREADS) {
        int n = e >> 8, k = e & 255;
        Whhs[n * SB + k] = __float2half_rn(w_hh[e]);
    }
    for (int e = tid; e < 256 * 32; e += NTHREADS) {
        int n = e >> 5, k = e & 31;
        Wihs[n * SWI + k] = __float2half_rn(w_ih[e]);
    }
    if (tid < 256) bs[tid] = b_ih[tid] + b_hh[tid];
    for (int e = tid; e < MT * SB; e += NTHREADS) Hs[e] = __float2half_rn(0.f);
    __syncthreads();

    for (int t = 0; t < T_; t++) {
        // stage x_t tile [128,32] fp32->fp16 (coalesced)
        #pragma unroll
        for (int i = 0; i < (MT * 32) / NTHREADS; i++) {
            int e = tid + i * NTHREADS;
            int r = e >> 5, c = e & 31;
            Xs[e] = __float2half_rn(x[(size_t)(b0 + r) * (T_ * I_) + t * I_ + c]);
        }
        __syncthreads();

        float acc[4][4][4];
        #pragma unroll
        for (int mi = 0; mi < 4; mi++)
            #pragma unroll
            for (int ni = 0; ni < 4; ni++)
                #pragma unroll
                for (int q = 0; q < 4; q++) acc[mi][ni][q] = 0.f;

        warp_gemm<32, 32, SWI>(Xs, Wihs, acc, wm, wn, lane);   // x_t @ Wih^T
        warp_gemm<256, SB, SB>(Hs, Whhs, acc, wm, wn, lane);   // h_{t-1} @ Whh^T
        __syncthreads();   // all Hs/Xs reads complete before overwrite

        #pragma unroll
        for (int mi = 0; mi < 4; mi++) {
            int r0 = wm * 64 + mi * 16 + grp;
            #pragma unroll
            for (int ni = 0; ni < 4; ni++) {
                int c0 = wn * 32 + ni * 8 + 2 * tig;
                float bb0 = bs[c0], bb1 = bs[c0 + 1];
                __half2 h01 = __floats2half2_rn(tanhf(acc[mi][ni][0] + bb0),
                                                tanhf(acc[mi][ni][1] + bb1));
                __half2 h23 = __floats2half2_rn(tanhf(acc[mi][ni][2] + bb0),
                                                tanhf(acc[mi][ni][3] + bb1));
                *(__half2*)&Hs[r0 * SB + c0]       = h01;
                *(__half2*)&Hs[(r0 + 8) * SB + c0] = h23;
                size_t g0 = ((size_t)(b0 + r0) * T_ + t) * H_ + c0;
                size_t g1 = ((size_t)(b0 + r0 + 8) * T_ + t) * H_ + c0;
                *(__half2*)&g_h1[g0] = h01;
                *(__half2*)&g_h1[g1] = h23;
            }
        }
        __syncthreads();   // h_t visible before next iteration's reads
    }
}

// ---------------------------------------------------------------------------
// Kernel 2: xw1 = h1 @ Wih1^T + (b_ih1+b_hh1), [B*T, 256] -> g_xw1 fp16
// grid 1024, each CTA does 4 M-tiles of 128 rows (amortizes W load)
// smem: Wih1 [256][264] fp16, A [128][264] fp16, bias 256 f32 => 203776 B
// ---------------------------------------------------------------------------
__global__ void __launch_bounds__(NTHREADS, 1)
proj1_kernel(const float* __restrict__ w_ih, const float* __restrict__ b_ih,
             const float* __restrict__ b_hh)
{
    extern __shared__ char sm[];
    __half* Ws = (__half*)sm;              // 256*SB
    __half* As = Ws + 256 * SB;            // MT*SB
    float*  bs = (float*)(As + MT * SB);   // 256

    const int tid = threadIdx.x;
    const int wid = tid >> 5, lane = tid & 31;
    const int wm = wid >> 3, wn = wid & 7;
    const int grp = lane >> 2, tig = lane & 3;

    for (int e = tid; e < 256 * 256; e += NTHREADS) {
        int n = e >> 8, k = e & 255;
        Ws[n * SB + k] = __float2half_rn(w_ih[e]);
    }
    if (tid < 256) bs[tid] = b_ih[tid] + b_hh[tid];

    for (int it = 0; it < 4; it++) {
        int tile = it * 1024 + blockIdx.x;
        size_t row0 = (size_t)tile * MT;

        // coalesced uint4 load of the 128x256 fp16 A-tile into padded smem
        const uint4* src = (const uint4*)(g_h1 + row0 * H_);
        #pragma unroll
        for (int i = 0; i < 8; i++) {
            int c = tid + i * NTHREADS;       // 4096 uint4 chunks
            int r = c >> 5, cp = c & 31;      // 32 uint4 per 256-half row
            *(uint4*)&As[r * SB + cp * 8] = src[c];
        }
        __syncthreads();                      // also covers Ws/bs on first iter

        float acc[4][4][4];
        #pragma unroll
        for (int mi = 0; mi < 4; mi++)
            #pragma unroll
            for (int ni = 0; ni < 4; ni++)
                #pragma unroll
                for (int q = 0; q < 4; q++) acc[mi][ni][q] = 0.f;

        warp_gemm<256, SB, SB>(As, Ws, acc, wm, wn, lane);

        #pragma unroll
        for (int mi = 0; mi < 4; mi++) {
            int r0 = wm * 64 + mi * 16 + grp;
            #pragma unroll
            for (int ni = 0; ni < 4; ni++) {
                int c0 = wn * 32 + ni * 8 + 2 * tig;
                float bb0 = bs[c0], bb1 = bs[c0 + 1];
                size_t g = (row0 + r0) * H_ + c0;
                *(__half2*)&g_xw1[g] =
                    __floats2half2_rn(acc[mi][ni][0] + bb0, acc[mi][ni][1] + bb1);
                *(__half2*)&g_xw1[g + 8 * H_] =
                    __floats2half2_rn(acc[mi][ni][2] + bb0, acc[mi][ni][3] + bb1);
            }
        }
        __syncthreads();   // A reads done before next tile overwrite
    }
}

// ---------------------------------------------------------------------------
// Kernel 3: layer1 recurrence + fused FC epilogue
// h2_t = tanh(xw1_t + h2_{t-1} @ Whh1^T); out += h2_t @ fc_w[:, t*256:(t+1)*256]^T
// smem: Whh1 [256][264], H [128][264], Fc [16][264] fp16 => 211200 B
// ---------------------------------------------------------------------------
__global__ void __launch_bounds__(NTHREADS, 1)
layer1_kernel(const float* __restrict__ w_hh, const float* __restrict__ fc_w,
              const float* __restrict__ fc_b, float* __restrict__ out)
{
    extern __shared__ char sm[];
    __half* Whhs = (__half*)sm;            // 256*SB
    __half* Hs   = Whhs + 256 * SB;        // MT*SB
    __half* Fs   = Hs + MT * SB;           // 16*SB  (rows 12..15 stay zero)

    const int tid = threadIdx.x;
    const int wid = tid >> 5, lane = tid & 31;
    const int wm = wid >> 3, wn = wid & 7;
    const int grp = lane >> 2, tig = lane & 3;
    const int b0 = blockIdx.x * MT;

    for (int e = tid; e < 256 * 256; e += NTHREADS) {
        int n = e >> 8, k = e & 255;
        Whhs[n * SB + k] = __float2half_rn(w_hh[e]);
    }
    for (int e = tid; e < MT * SB; e += NTHREADS) Hs[e] = __float2half_rn(0.f);
    for (int e = tid; e < 16 * SB; e += NTHREADS) Fs[e] = __float2half_rn(0.f);
    __syncthreads();

    float accfc[4][4];
    #pragma unroll
    for (int mi = 0; mi < 4; mi++)
        #pragma unroll
        for (int q = 0; q < 4; q++) accfc[mi][q] = 0.f;

    for (int t = 0; t < T_; t++) {
        // init accumulators from g_xw1 (bias already included)
        float acc[4][4][4];
        #pragma unroll
        for (int mi = 0; mi < 4; mi++) {
            int r0 = wm * 64 + mi * 16 + grp;
            #pragma unroll
            for (int ni = 0; ni < 4; ni++) {
                int c0 = wn * 32 + ni * 8 + 2 * tig;
                size_t g0 = ((size_t)(b0 + r0) * T_ + t) * H_ + c0;
                float2 f0 = __half22float2(*(const __half2*)&g_xw1[g0]);
                float2 f1 = __half22float2(*(const __half2*)&g_xw1[g0 + (size_t)8 * T_ * H_]);
                acc[mi][ni][0] = f0.x; acc[mi][ni][1] = f0.y;
                acc[mi][ni][2] = f1.x; acc[mi][ni][3] = f1.y;
            }
        }

        warp_gemm<256, SB, SB>(Hs, Whhs, acc, wm, wn, lane);
        __syncthreads();   // Hs reads (gemm) + Fs reads (prev FC) complete

        // tanh + publish h_t
        #pragma unroll
        for (int mi = 0; mi < 4; mi++) {
            int r0 = wm * 64 + mi * 16 + grp;
            #pragma unroll
            for (int ni = 0; ni < 4; ni++) {
                int c0 = wn * 32 + ni * 8 + 2 * tig;
                *(__half2*)&Hs[r0 * SB + c0] =
                    __floats2half2_rn(tanhf(acc[mi][ni][0]), tanhf(acc[mi][ni][1]));
                *(__half2*)&Hs[(r0 + 8) * SB + c0] =
                    __floats2half2_rn(tanhf(acc[mi][ni][2]), tanhf(acc[mi][ni][3]));
            }
        }
        // stage fc_w slice for this timestep: [12][256] fp32 -> fp16
        #pragma unroll
        for (int i = 0; i < 6; i++) {
            int e = tid + i * NTHREADS;       // 3072
            int c = e >> 8, j = e & 255;
            Fs[c * SB + j] = __float2half_rn(fc_w[(size_t)c * (T_ * H_) + t * H_ + j]);
        }
        __syncthreads();   // h_t and fc slice ready

        // FC side-mma: warps 0..3, out-tile 64x8 each (cols 0..15, cols>=12 are zero)
        if (wid < 4) {
            int wm2 = wid >> 1, wn2 = wid & 1;
            #pragma unroll
            for (int k0 = 0; k0 < 256; k0 += 16) {
                const __half* bp = Fs + (wn2 * 8 + grp) * SB + k0 + 2 * tig;
                uint32_t b[2] = { ldb32(bp), ldb32(bp + 8) };
                #pragma unroll
                for (int mi = 0; mi < 4; mi++) {
                    const __half* ap = Hs + (wm2 * 64 + mi * 16 + grp) * SB + k0 + 2 * tig;
                    uint32_t a[4] = { ldb32(ap), ldb32(ap + 8 * SB),
                                      ldb32(ap + 8), ldb32(ap + 8 * SB + 8) };
                    mma16816(accfc[mi], a, b);
                }
            }
        }
    }

    // write logits
    if (wid < 4) {
        int wm2 = wid >> 1, wn2 = wid & 1;
        #pragma unroll
        for (int mi = 0; mi < 4; mi++) {
            int r = b0 + wm2 * 64 + mi * 16 + grp;
            int c0 = wn2 * 8 + 2 * tig;
            if (c0 < C_)     out[(size_t)r * C_ + c0]           = accfc[mi][0] + fc_b[c0];
            if (c0 + 1 < C_) out[(size_t)r * C_ + c0 + 1]       = accfc[mi][1] + fc_b[c0 + 1];
            if (c0 < C_)     out[(size_t)(r + 8) * C_ + c0]     = accfc[mi][2] + fc_b[c0];
            if (c0 + 1 < C_) out[(size_t)(r + 8) * C_ + c0 + 1] = accfc[mi][3] + fc_b[c0 + 1];
        }
    }
}

// ---------------------------------------------------------------------------
extern "C" void kernel_launch(void* const* d_in, const int* in_sizes, int n_in,
                              void* d_out, int out_size)
{
    const float* x     = (const float*)d_in[0];
    const float* w_ih0 = (const float*)d_in[1];
    const float* w_hh0 = (const float*)d_in[2];
    const float* b_ih0 = (const float*)d_in[3];
    const float* b_hh0 = (const float*)d_in[4];
    const float* w_ih1 = (const float*)d_in[5];
    const float* w_hh1 = (const float*)d_in[6];
    const float* b_ih1 = (const float*)d_in[7];
    const float* b_hh1 = (const float*)d_in[8];
    const float* fc_w  = (const float*)d_in[9];
    const float* fc_b  = (const float*)d_in[10];
    float* out = (float*)d_out;

    const int smem0 = (256 * SB + MT * SB + 256 * SWI + MT * 32) * 2 + 256 * 4; // 230400
    const int smem2 = (256 * SB + MT * SB) * 2 + 256 * 4;                       // 203776
    const int smem1 = (256 * SB + MT * SB + 16 * SB) * 2;                       // 211200

    cudaFuncSetAttribute(layer0_kernel, cudaFuncAttributeMaxDynamicSharedMemorySize, smem0);
    cudaFuncSetAttribute(proj1_kernel,  cudaFuncAttributeMaxDynamicSharedMemorySize, smem2);
    cudaFuncSetAttribute(layer1_kernel, cudaFuncAttributeMaxDynamicSharedMemorySize, smem1);

    layer0_kernel<<<B_ / MT, NTHREADS, smem0>>>(x, w_ih0, w_hh0, b_ih0, b_hh0);
    proj1_kernel<<<1024, NTHREADS, smem2>>>(w_ih1, b_ih1, b_hh1);
    layer1_kernel<<<B_ / MT, NTHREADS, smem1>>>(w_hh1, fc_w, fc_b, out);
}

// round 6
// speedup vs baseline: 1.1486x; 1.1486x over previous
#include <cuda_runtime.h>
#include <cuda_fp16.h>
#include <stdint.h>

// Problem constants
#define B_ 16384
#define T_ 32
#define I_ 32
#define H_ 256
#define C_ 12

#define MT 128          // batch-tile rows per CTA
#define NTHREADS 512    // 16 warps: 2 (M) x 8 (N)
#define SB 264          // padded smem stride (halfs) for 256-wide rows (conflict-free)
#define SWI 36          // padded stride for w_ih0 (32-wide rows)

// Inter-layer scratch (static device globals; no runtime allocation)
__device__ __align__(16) __half g_h1 [(size_t)B_ * T_ * H_];   // layer0 output, fp16
__device__ __align__(16) __half g_xw1[(size_t)B_ * T_ * H_];   // layer1 input projection, fp16

// ---------------------------------------------------------------------------
// primitives
// ---------------------------------------------------------------------------
__device__ __forceinline__ void mma16816(float c[4], const uint32_t a[4], const uint32_t b[2]) {
    asm volatile(
        "mma.sync.aligned.m16n8k16.row.col.f32.f16.f16.f32 "
        "{%0,%1,%2,%3}, {%4,%5,%6,%7}, {%8,%9}, {%0,%1,%2,%3};\n"
        : "+f"(c[0]), "+f"(c[1]), "+f"(c[2]), "+f"(c[3])
        : "r"(a[0]), "r"(a[1]), "r"(a[2]), "r"(a[3]), "r"(b[0]), "r"(b[1]));
}

__device__ __forceinline__ uint32_t ldb32(const __half* p) { return *(const uint32_t*)p; }

// hardware tanh on fp32 (MUFU.TANH): no fp16 input quantization, approx err ~2^-11 rel
__device__ __forceinline__ float tanh_f32(float x) {
    float y;
    asm("tanh.approx.f32 %0, %1;" : "=f"(y) : "f"(x));
    return y;
}
__device__ __forceinline__ uint32_t pack_h2(float a, float b) {
    __half2 h = __floats2half2_rn(a, b);
    return *reinterpret_cast<uint32_t*>(&h);
}
__device__ __forceinline__ uint32_t tanh2_pack(float a, float b) {
    return pack_h2(tanh_f32(a), tanh_f32(b));
}

// acc[mi][ni][4] += A[128 x KTOT] * B^T, where Bs is [256][KTOT] row-major (n,k)
// Warp tile: 64 (M) x 32 (N); scalar-LDS fragment loads (known-good).
template<int KTOT, int AST, int BST>
__device__ __forceinline__ void warp_gemm(const __half* __restrict__ As,
                                          const __half* __restrict__ Bs,
                                          float (&acc)[4][4][4],
                                          int wm, int wn, int lane)
{
    const int grp = lane >> 2, tig = lane & 3;
    #pragma unroll
    for (int k0 = 0; k0 < KTOT; k0 += 16) {
        uint32_t a[4][4];
        #pragma unroll
        for (int mi = 0; mi < 4; mi++) {
            const __half* ap = As + (wm * 64 + mi * 16 + grp) * AST + k0 + 2 * tig;
            a[mi][0] = ldb32(ap);
            a[mi][1] = ldb32(ap + 8 * AST);
            a[mi][2] = ldb32(ap + 8);
            a[mi][3] = ldb32(ap + 8 * AST + 8);
        }
        #pragma unroll
        for (int ni = 0; ni < 4; ni++) {
            const __half* bp = Bs + (wn * 32 + ni * 8 + grp) * BST + k0 + 2 * tig;
            uint32_t b[2];
            b[0] = ldb32(bp);
            b[1] = ldb32(bp + 8);
            #pragma unroll
            for (int mi = 0; mi < 4; mi++)
                mma16816(acc[mi][ni], a[mi], b);
        }
    }
}

// ---------------------------------------------------------------------------
// Kernel 1: layer0 fused (input projection + recurrence), h1 -> g_h1 (fp16)
// ---------------------------------------------------------------------------
__global__ void __launch_bounds__(NTHREADS, 1)
layer0_kernel(const float* __restrict__ x, const float* __restrict__ w_ih,
              const float* __restrict__ w_hh, const float* __restrict__ b_ih,
              const float* __restrict__ b_hh)
{
    extern __shared__ char sm[];
    __half* Whhs = (__half*)sm;               // 256*SB
    __half* Hs   = Whhs + 256 * SB;           // MT*SB
    __half* Wihs = Hs + MT * SB;              // 256*SWI
    __half* Xs   = Wihs + 256 * SWI;          // MT*32
    float*  bs   = (float*)(Xs + MT * 32);    // 256

    const int tid = threadIdx.x;
    const int wid = tid >> 5, lane = tid & 31;
    const int wm = wid >> 3, wn = wid & 7;
    const int grp = lane >> 2, tig = lane & 3;
    const int b0 = blockIdx.x * MT;

    for (int e = tid; e < 256 * 256; e += NTHREADS) {
        int n = e >> 8, k = e & 255;
        Whhs[n * SB + k] = __float2half_rn(w_hh[e]);
    }
    for (int e = tid; e < 256 * 32; e += NTHREADS) {
        int n = e >> 5, k = e & 31;
        Wihs[n * SWI + k] = __float2half_rn(w_ih[e]);
    }
    if (tid < 256) bs[tid] = b_ih[tid] + b_hh[tid];
    for (int e = tid; e < MT * SB; e += NTHREADS) Hs[e] = __float2half_rn(0.f);

    // stage x_0: each thread covers 2 float4 (8 floats) of the 128x32 tile
    const int r0i = tid >> 3, q0 = tid & 7;
    const int r1i = (tid + 512) >> 3, q1 = tid & 7;
    {
        float4 p0 = *(const float4*)(x + (size_t)(b0 + r0i) * (T_ * I_) + q0 * 4);
        float4 p1 = *(const float4*)(x + (size_t)(b0 + r1i) * (T_ * I_) + q1 * 4);
        *(uint2*)&Xs[r0i * 32 + q0 * 4] = make_uint2(pack_h2(p0.x, p0.y), pack_h2(p0.z, p0.w));
        *(uint2*)&Xs[r1i * 32 + q1 * 4] = make_uint2(pack_h2(p1.x, p1.y), pack_h2(p1.z, p1.w));
    }
    __syncthreads();

    for (int t = 0; t < T_; t++) {
        // prefetch x_{t+1} into registers (in flight during gemm)
        float4 p0, p1;
        if (t < T_ - 1) {
            p0 = *(const float4*)(x + (size_t)(b0 + r0i) * (T_ * I_) + (t + 1) * I_ + q0 * 4);
            p1 = *(const float4*)(x + (size_t)(b0 + r1i) * (T_ * I_) + (t + 1) * I_ + q1 * 4);
        }

        float acc[4][4][4];
        #pragma unroll
        for (int mi = 0; mi < 4; mi++)
            #pragma unroll
            for (int ni = 0; ni < 4; ni++)
                #pragma unroll
                for (int q = 0; q < 4; q++) acc[mi][ni][q] = 0.f;

        warp_gemm<32, 32, SWI>(Xs, Wihs, acc, wm, wn, lane);   // x_t @ Wih^T
        warp_gemm<256, SB, SB>(Hs, Whhs, acc, wm, wn, lane);   // h_{t-1} @ Whh^T
        __syncthreads();   // all Hs/Xs reads complete before overwrite

        // stage prefetched x_{t+1}
        if (t < T_ - 1) {
            *(uint2*)&Xs[r0i * 32 + q0 * 4] = make_uint2(pack_h2(p0.x, p0.y), pack_h2(p0.z, p0.w));
            *(uint2*)&Xs[r1i * 32 + q1 * 4] = make_uint2(pack_h2(p1.x, p1.y), pack_h2(p1.z, p1.w));
        }

        // epilogue: bias + MUFU tanh on fp32, publish h_t
        #pragma unroll
        for (int mi = 0; mi < 4; mi++) {
            int r0 = wm * 64 + mi * 16 + grp;
            #pragma unroll
            for (int ni = 0; ni < 4; ni++) {
                int c0 = wn * 32 + ni * 8 + 2 * tig;
                float bb0 = bs[c0], bb1 = bs[c0 + 1];
                uint32_t h01 = tanh2_pack(acc[mi][ni][0] + bb0, acc[mi][ni][1] + bb1);
                uint32_t h23 = tanh2_pack(acc[mi][ni][2] + bb0, acc[mi][ni][3] + bb1);
                *(uint32_t*)&Hs[r0 * SB + c0]       = h01;
                *(uint32_t*)&Hs[(r0 + 8) * SB + c0] = h23;
                size_t g0 = ((size_t)(b0 + r0) * T_ + t) * H_ + c0;
                size_t g1 = ((size_t)(b0 + r0 + 8) * T_ + t) * H_ + c0;
                *(uint32_t*)&g_h1[g0] = h01;
                *(uint32_t*)&g_h1[g1] = h23;
            }
        }
        __syncthreads();   // h_t / x_{t+1} visible before next iteration's reads
    }
}

// ---------------------------------------------------------------------------
// Kernel 2: xw1 = h1 @ Wih1^T + (b_ih1+b_hh1), [B*T, 256] -> g_xw1 fp16
// ---------------------------------------------------------------------------
__global__ void __launch_bounds__(NTHREADS, 1)
proj1_kernel(const float* __restrict__ w_ih, const float* __restrict__ b_ih,
             const float* __restrict__ b_hh)
{
    extern __shared__ char sm[];
    __half* Ws = (__half*)sm;              // 256*SB
    __half* As = Ws + 256 * SB;            // MT*SB
    float*  bs = (float*)(As + MT * SB);   // 256

    const int tid = threadIdx.x;
    const int wid = tid >> 5, lane = tid & 31;
    const int wm = wid >> 3, wn = wid & 7;
    const int grp = lane >> 2, tig = lane & 3;

    for (int e = tid; e < 256 * 256; e += NTHREADS) {
        int n = e >> 8, k = e & 255;
        Ws[n * SB + k] = __float2half_rn(w_ih[e]);
    }
    if (tid < 256) bs[tid] = b_ih[tid] + b_hh[tid];

    for (int it = 0; it < 4; it++) {
        int tile = it * 1024 + blockIdx.x;
        size_t row0 = (size_t)tile * MT;

        // coalesced uint4 load of the 128x256 fp16 A-tile into padded smem
        const uint4* src = (const uint4*)(g_h1 + row0 * H_);
        #pragma unroll
        for (int i = 0; i < 8; i++) {
            int c = tid + i * NTHREADS;       // 4096 uint4 chunks
            int r = c >> 5, cp = c & 31;      // 32 uint4 per 256-half row
            *(uint4*)&As[r * SB + cp * 8] = src[c];
        }
        __syncthreads();                      // also covers Ws/bs on first iter

        float acc[4][4][4];
        #pragma unroll
        for (int mi = 0; mi < 4; mi++)
            #pragma unroll
            for (int ni = 0; ni < 4; ni++)
                #pragma unroll
                for (int q = 0; q < 4; q++) acc[mi][ni][q] = 0.f;

        warp_gemm<256, SB, SB>(As, Ws, acc, wm, wn, lane);

        #pragma unroll
        for (int mi = 0; mi < 4; mi++) {
            int r0 = wm * 64 + mi * 16 + grp;
            #pragma unroll
            for (int ni = 0; ni < 4; ni++) {
                int c0 = wn * 32 + ni * 8 + 2 * tig;
                float bb0 = bs[c0], bb1 = bs[c0 + 1];
                size_t g = (row0 + r0) * H_ + c0;
                *(uint32_t*)&g_xw1[g] = pack_h2(acc[mi][ni][0] + bb0, acc[mi][ni][1] + bb1);
                *(uint32_t*)&g_xw1[g + 8 * H_] = pack_h2(acc[mi][ni][2] + bb0, acc[mi][ni][3] + bb1);
            }
        }
        __syncthreads();   // A reads done before next tile overwrite
    }
}

// ---------------------------------------------------------------------------
// Kernel 3: layer1 recurrence + fused FC epilogue
// ---------------------------------------------------------------------------
__global__ void __launch_bounds__(NTHREADS, 1)
layer1_kernel(const float* __restrict__ w_hh, const float* __restrict__ fc_w,
              const float* __restrict__ fc_b, float* __restrict__ out)
{
    extern __shared__ char sm[];
    __half* Whhs = (__half*)sm;            // 256*SB
    __half* Hs   = Whhs + 256 * SB;        // MT*SB
    __half* Fs   = Hs + MT * SB;           // 16*SB  (rows 12..15 stay zero)

    const int tid = threadIdx.x;
    const int wid = tid >> 5, lane = tid & 31;
    const int wm = wid >> 3, wn = wid & 7;
    const int grp = lane >> 2, tig = lane & 3;
    const int b0 = blockIdx.x * MT;

    for (int e = tid; e < 256 * 256; e += NTHREADS) {
        int n = e >> 8, k = e & 255;
        Whhs[n * SB + k] = __float2half_rn(w_hh[e]);
    }
    for (int e = tid; e < MT * SB; e += NTHREADS) Hs[e] = __float2half_rn(0.f);
    for (int e = tid; e < 16 * SB; e += NTHREADS) Fs[e] = __float2half_rn(0.f);
    __syncthreads();

    float accfc[4][4];
    #pragma unroll
    for (int mi = 0; mi < 4; mi++)
        #pragma unroll
        for (int q = 0; q < 4; q++) accfc[mi][q] = 0.f;

    for (int t = 0; t < T_; t++) {
        // init accumulators from g_xw1 (bias already included)
        float acc[4][4][4];
        #pragma unroll
        for (int mi = 0; mi < 4; mi++) {
            int r0 = wm * 64 + mi * 16 + grp;
            #pragma unroll
            for (int ni = 0; ni < 4; ni++) {
                int c0 = wn * 32 + ni * 8 + 2 * tig;
                size_t g0 = ((size_t)(b0 + r0) * T_ + t) * H_ + c0;
                float2 f0 = __half22float2(*(const __half2*)&g_xw1[g0]);
                float2 f1 = __half22float2(*(const __half2*)&g_xw1[g0 + (size_t)8 * T_ * H_]);
                acc[mi][ni][0] = f0.x; acc[mi][ni][1] = f0.y;
                acc[mi][ni][2] = f1.x; acc[mi][ni][3] = f1.y;
            }
        }

        warp_gemm<256, SB, SB>(Hs, Whhs, acc, wm, wn, lane);
        __syncthreads();   // Hs reads (gemm t) + Hs/Fs reads (FC of t-1) complete

        // tanh (MUFU fp32) + publish h_t
        #pragma unroll
        for (int mi = 0; mi < 4; mi++) {
            int r0 = wm * 64 + mi * 16 + grp;
            #pragma unroll
            for (int ni = 0; ni < 4; ni++) {
                int c0 = wn * 32 + ni * 8 + 2 * tig;
                *(uint32_t*)&Hs[r0 * SB + c0] =
                    tanh2_pack(acc[mi][ni][0], acc[mi][ni][1]);
                *(uint32_t*)&Hs[(r0 + 8) * SB + c0] =
                    tanh2_pack(acc[mi][ni][2], acc[mi][ni][3]);
            }
        }
        // stage fc_w slice for this timestep: [12][256] fp32 -> fp16
        #pragma unroll
        for (int i = 0; i < 6; i++) {
            int e = tid + i * NTHREADS;       // 3072
            int c = e >> 8, j = e & 255;
            Fs[c * SB + j] = __float2half_rn(fc_w[(size_t)c * (T_ * H_) + t * H_ + j]);
        }
        __syncthreads();   // h_t and fc slice ready

        // FC side-mma: warps 0..3, out-tile 64x8 each (cols 0..15, cols>=12 are zero)
        if (wid < 4) {
            int wm2 = wid >> 1, wn2 = wid & 1;
            #pragma unroll
            for (int k0 = 0; k0 < 256; k0 += 16) {
                const __half* bp = Fs + (wn2 * 8 + grp) * SB + k0 + 2 * tig;
                uint32_t b[2] = { ldb32(bp), ldb32(bp + 8) };
                #pragma unroll
                for (int mi = 0; mi < 4; mi++) {
                    const __half* ap = Hs + (wm2 * 64 + mi * 16 + grp) * SB + k0 + 2 * tig;
                    uint32_t a[4] = { ldb32(ap), ldb32(ap + 8 * SB),
                                      ldb32(ap + 8), ldb32(ap + 8 * SB + 8) };
                    mma16816(accfc[mi], a, b);
                }
            }
        }
    }

    // write logits
    if (wid < 4) {
        int wm2 = wid >> 1, wn2 = wid & 1;
        #pragma unroll
        for (int mi = 0; mi < 4; mi++) {
            int r = b0 + wm2 * 64 + mi * 16 + grp;
            int c0 = wn2 * 8 + 2 * tig;
            if (c0 < C_)     out[(size_t)r * C_ + c0]           = accfc[mi][0] + fc_b[c0];
            if (c0 + 1 < C_) out[(size_t)r * C_ + c0 + 1]       = accfc[mi][1] + fc_b[c0 + 1];
            if (c0 < C_)     out[(size_t)(r + 8) * C_ + c0]     = accfc[mi][2] + fc_b[c0];
            if (c0 + 1 < C_) out[(size_t)(r + 8) * C_ + c0 + 1] = accfc[mi][3] + fc_b[c0 + 1];
        }
    }
}

// ---------------------------------------------------------------------------
extern "C" void kernel_launch(void* const* d_in, const int* in_sizes, int n_in,
                              void* d_out, int out_size)
{
    const float* x     = (const float*)d_in[0];
    const float* w_ih0 = (const float*)d_in[1];
    const float* w_hh0 = (const float*)d_in[2];
    const float* b_ih0 = (const float*)d_in[3];
    const float* b_hh0 = (const float*)d_in[4];
    const float* w_ih1 = (const float*)d_in[5];
    const float* w_hh1 = (const float*)d_in[6];
    const float* b_ih1 = (const float*)d_in[7];
    const float* b_hh1 = (const float*)d_in[8];
    const float* fc_w  = (const float*)d_in[9];
    const float* fc_b  = (const float*)d_in[10];
    float* out = (float*)d_out;

    const int smem0 = (256 * SB + MT * SB + 256 * SWI + MT * 32) * 2 + 256 * 4; // 230400
    const int smem2 = (256 * SB + MT * SB) * 2 + 256 * 4;                       // 203776
    const int smem1 = (256 * SB + MT * SB + 16 * SB) * 2;                       // 211200

    cudaFuncSetAttribute(layer0_kernel, cudaFuncAttributeMaxDynamicSharedMemorySize, smem0);
    cudaFuncSetAttribute(proj1_kernel,  cudaFuncAttributeMaxDynamicSharedMemorySize, smem2);
    cudaFuncSetAttribute(layer1_kernel, cudaFuncAttributeMaxDynamicSharedMemorySize, smem1);

    layer0_kernel<<<B_ / MT, NTHREADS, smem0>>>(x, w_ih0, w_hh0, b_ih0, b_hh0);
    proj1_kernel<<<1024, NTHREADS, smem2>>>(w_ih1, b_ih1, b_hh1);
    layer1_kernel<<<B_ / MT, NTHREADS, smem1>>>(w_hh1, fc_w, fc_b, out);
}